// round 1
// baseline (speedup 1.0000x reference)
#include <cuda_runtime.h>
#include <cuda_bf16.h>
#include <cstdint>

// Problem constants
#define BB 2
#define SS 2048
#define DD 1024
#define RR 128
#define HH 16
#define NN 16
#define DH 64
#define TOK (BB*SS)          // 4096
#define NR (NN*RR)           // 2048

// ---------------- scratch (device globals; allocation-free) ----------------
__device__ __align__(256) float g_Ft[DD * NR];        // transposed feature mat (D, N*R)  8MB
__device__ __align__(256) float g_tqk[TOK * NR];      // t for f_qk (tok, n, r)          32MB
__device__ __align__(256) float g_tv [TOK * NR];      // t for f_v                        32MB
__device__ __align__(256) float g_wh [TOK * NR];      // wh scratch (reused Q/K/V)        32MB
__device__ __align__(256) float g_Q  [TOK * DD];
__device__ __align__(256) float g_K  [TOK * DD];
__device__ __align__(256) float g_V  [TOK * DD];
__device__ __align__(256) float g_At [TOK * DD];      // attention output (tok, D)
__device__ __align__(256) float g_WOt[DD * DD];       // W_O transposed

// ---------------- transpose f: (N,D,R) -> (D, N*R) ----------------
__global__ void transpose_f_kernel(const float* __restrict__ f, float* __restrict__ Ft) {
    int idx = blockIdx.x * 256 + threadIdx.x;      // over N*D*R = 2^21
    int r = idx & (RR - 1);
    int d = (idx >> 7) & (DD - 1);
    int n = idx >> 17;
    Ft[d * NR + n * RR + r] = f[idx];
}

// ---------------- transpose square (1024x1024) ----------------
__global__ void transpose_sq_kernel(const float* __restrict__ A, float* __restrict__ At, int n) {
    __shared__ float tile[32][33];
    int x = blockIdx.x * 32 + threadIdx.x;
    int y0 = blockIdx.y * 32;
    for (int i = threadIdx.y; i < 32; i += 8)
        tile[i][threadIdx.x] = A[(size_t)(y0 + i) * n + x];
    __syncthreads();
    int x2 = blockIdx.y * 32 + threadIdx.x;
    int y2 = blockIdx.x * 32;
    for (int i = threadIdx.y; i < 32; i += 8)
        At[(size_t)(y2 + i) * n + x2] = tile[threadIdx.x][i];
}

// ---------------- mix: h = sum_n wf*t ; wh = wr (outer) h ----------------
// t: (TOK, N, R), wf/wr: (TOK, N), wh: (TOK, N*R)
__global__ void mix_kernel(const float* __restrict__ t,
                           const float* __restrict__ wf,
                           const float* __restrict__ wr,
                           float* __restrict__ wh) {
    int tok = blockIdx.x;
    int r = threadIdx.x;   // 0..127
    const float* tp = t + (size_t)tok * NR;
    float h = 0.f;
#pragma unroll
    for (int n = 0; n < NN; n++) h += wf[tok * NN + n] * tp[n * RR + r];
#pragma unroll
    for (int n = 0; n < NN; n++)
        wh[(size_t)tok * NR + n * RR + r] = wr[tok * NN + n] * h;
}

// ---------------- fp32 tiled GEMM: C(MxN) = A(MxK) @ B(KxN), row-major ----
// 128x128 tile, BK=16, 256 threads, 8x8 per thread. M%128==0, N%128==0, K%16==0.
__global__ __launch_bounds__(256) void sgemm_kernel(
        const float* __restrict__ A, const float* __restrict__ B,
        float* __restrict__ C, int M, int N, int K) {
    __shared__ float As[128][17];
    __shared__ float Bs[16][128];
    const int tid = threadIdx.x;
    const int tx = tid & 15;        // 0..15  (col groups of 8)
    const int ty = tid >> 4;        // 0..15  (row groups of 8)
    const int brow = blockIdx.y * 128;
    const int bcol = blockIdx.x * 128;

    float acc[8][8];
#pragma unroll
    for (int i = 0; i < 8; i++)
#pragma unroll
        for (int j = 0; j < 8; j++) acc[i][j] = 0.f;

    for (int k0 = 0; k0 < K; k0 += 16) {
        // load A tile: 128 rows x 16 cols = 512 float4
#pragma unroll
        for (int l = 0; l < 2; ++l) {
            int f = tid + l * 256;
            int row = f >> 2;
            int c4 = (f & 3) * 4;
            float4 v = *reinterpret_cast<const float4*>(
                &A[(size_t)(brow + row) * K + k0 + c4]);
            As[row][c4 + 0] = v.x; As[row][c4 + 1] = v.y;
            As[row][c4 + 2] = v.z; As[row][c4 + 3] = v.w;
        }
        // load B tile: 16 rows x 128 cols = 512 float4
#pragma unroll
        for (int l = 0; l < 2; ++l) {
            int f = tid + l * 256;
            int row = f >> 5;
            int c = (f & 31) * 4;
            *reinterpret_cast<float4*>(&Bs[row][c]) =
                *reinterpret_cast<const float4*>(&B[(size_t)(k0 + row) * N + bcol + c]);
        }
        __syncthreads();
#pragma unroll
        for (int k = 0; k < 16; ++k) {
            float a[8], b[8];
#pragma unroll
            for (int i = 0; i < 8; i++) a[i] = As[ty * 8 + i][k];
            float4 b0 = *reinterpret_cast<float4*>(&Bs[k][tx * 8]);
            float4 b1 = *reinterpret_cast<float4*>(&Bs[k][tx * 8 + 4]);
            b[0] = b0.x; b[1] = b0.y; b[2] = b0.z; b[3] = b0.w;
            b[4] = b1.x; b[5] = b1.y; b[6] = b1.z; b[7] = b1.w;
#pragma unroll
            for (int i = 0; i < 8; i++)
#pragma unroll
                for (int j = 0; j < 8; j++) acc[i][j] += a[i] * b[j];
        }
        __syncthreads();
    }
#pragma unroll
    for (int i = 0; i < 8; i++) {
        float4 o0 = make_float4(acc[i][0], acc[i][1], acc[i][2], acc[i][3]);
        float4 o1 = make_float4(acc[i][4], acc[i][5], acc[i][6], acc[i][7]);
        size_t base = (size_t)(brow + ty * 8 + i) * N + bcol + tx * 8;
        *reinterpret_cast<float4*>(&C[base]) = o0;
        *reinterpret_cast<float4*>(&C[base + 4]) = o1;
    }
}

// ---------------- causal flash attention (fp32) ----------------
// Q/K/V: (TOK, D) with head h occupying cols [h*64, h*64+64). Out same layout.
// grid: (S/64, B*H), block: 128 threads (tx=tid%8 owns 8 cols, ty=tid/8 owns 4 rows)
#define ATTN_SMEM ((4 * 64 * 65 + 3 * 64) * 4)
__global__ __launch_bounds__(128) void attn_kernel(
        const float* __restrict__ Q, const float* __restrict__ K,
        const float* __restrict__ V, float* __restrict__ O) {
    extern __shared__ float sm[];
    float* Qs = sm;                    // [64][65]
    float* Ks = Qs + 64 * 65;          // [64][65]
    float* Vs = Ks + 64 * 65;          // [64][65]
    float* Ps = Vs + 64 * 65;          // [64][65]
    float* Mrow = Ps + 64 * 65;        // [64]
    float* Lrow = Mrow + 64;           // [64]
    float* Arow = Lrow + 64;           // [64]

    const int qt = blockIdx.x;         // query tile 0..31
    const int bh = blockIdx.y;         // 0..31
    const int b = bh >> 4;
    const int h = bh & 15;
    const int tid = threadIdx.x;
    const int tx = tid & 7;            // 8 col-groups
    const int ty = tid >> 3;           // 16 row-groups (4 rows each)
    const float scale = 0.125f;        // 1/sqrt(64)

    const size_t headoff = (size_t)h * DH;
    const size_t batchoff = (size_t)b * SS;

    // load Q tile
    for (int i = tid; i < 64 * 64; i += 128) {
        int m = i >> 6, k = i & 63;
        Qs[m * 65 + k] = Q[(batchoff + qt * 64 + m) * DD + headoff + k];
    }
    for (int m = tid; m < 64; m += 128) { Mrow[m] = -1e30f; Lrow[m] = 0.f; }

    float Oacc[4][8];
#pragma unroll
    for (int i = 0; i < 4; i++)
#pragma unroll
        for (int j = 0; j < 8; j++) Oacc[i][j] = 0.f;
    __syncthreads();

    for (int jt = 0; jt <= qt; ++jt) {
        for (int i = tid; i < 64 * 64; i += 128) {
            int n = i >> 6, k = i & 63;
            size_t src = (batchoff + jt * 64 + n) * DD + headoff + k;
            Ks[n * 65 + k] = K[src];
            Vs[n * 65 + k] = V[src];
        }
        __syncthreads();

        // scores: s[i][j] = q(row ty*4+i) . k(col tx*8+j)
        float s[4][8];
#pragma unroll
        for (int i = 0; i < 4; i++)
#pragma unroll
            for (int j = 0; j < 8; j++) s[i][j] = 0.f;
        for (int k = 0; k < 64; ++k) {
            float qv[4], kv[8];
#pragma unroll
            for (int i = 0; i < 4; i++) qv[i] = Qs[(ty * 4 + i) * 65 + k];
#pragma unroll
            for (int j = 0; j < 8; j++) kv[j] = Ks[(tx * 8 + j) * 65 + k];
#pragma unroll
            for (int i = 0; i < 4; i++)
#pragma unroll
                for (int j = 0; j < 8; j++) s[i][j] += qv[i] * kv[j];
        }
        // scale + causal mask (only diagonal tile partial)
#pragma unroll
        for (int i = 0; i < 4; i++)
#pragma unroll
            for (int j = 0; j < 8; j++) {
                s[i][j] *= scale;
                if (jt == qt && (tx * 8 + j) > (ty * 4 + i)) s[i][j] = -1e30f;
            }
        // row max across 8 col-group threads
        float rmax[4];
#pragma unroll
        for (int i = 0; i < 4; i++) {
            float m = s[i][0];
#pragma unroll
            for (int j = 1; j < 8; j++) m = fmaxf(m, s[i][j]);
            m = fmaxf(m, __shfl_xor_sync(0xffffffffu, m, 1));
            m = fmaxf(m, __shfl_xor_sync(0xffffffffu, m, 2));
            m = fmaxf(m, __shfl_xor_sync(0xffffffffu, m, 4));
            rmax[i] = m;
        }
        float rsum[4];
#pragma unroll
        for (int i = 0; i < 4; i++) {
            int row = ty * 4 + i;
            float mnew = fmaxf(Mrow[row], rmax[i]);
            float ssum = 0.f;
#pragma unroll
            for (int j = 0; j < 8; j++) {
                float p = __expf(s[i][j] - mnew);
                Ps[row * 65 + tx * 8 + j] = p;
                ssum += p;
            }
            ssum += __shfl_xor_sync(0xffffffffu, ssum, 1);
            ssum += __shfl_xor_sync(0xffffffffu, ssum, 2);
            ssum += __shfl_xor_sync(0xffffffffu, ssum, 4);
            rsum[i] = ssum;
            if (tx == 0) {
                float alpha = __expf(Mrow[row] - mnew);
                Arow[row] = alpha;
                Lrow[row] = Lrow[row] * alpha + ssum;
                Mrow[row] = mnew;
            }
        }
        (void)rsum;
        __syncthreads();

        // O = O*alpha + P @ V   (thread owns rows ty*4.., d cols tx*8..)
        float a[4];
#pragma unroll
        for (int i = 0; i < 4; i++) a[i] = Arow[ty * 4 + i];
#pragma unroll
        for (int i = 0; i < 4; i++)
#pragma unroll
            for (int j = 0; j < 8; j++) Oacc[i][j] *= a[i];
        for (int n = 0; n < 64; ++n) {
            float pv[4], vv[8];
#pragma unroll
            for (int i = 0; i < 4; i++) pv[i] = Ps[(ty * 4 + i) * 65 + n];
#pragma unroll
            for (int j = 0; j < 8; j++) vv[j] = Vs[n * 65 + tx * 8 + j];
#pragma unroll
            for (int i = 0; i < 4; i++)
#pragma unroll
                for (int j = 0; j < 8; j++) Oacc[i][j] += pv[i] * vv[j];
        }
        __syncthreads();
    }

    // epilogue: divide by L and write (tok, D) layout
#pragma unroll
    for (int i = 0; i < 4; i++) {
        int row = ty * 4 + i;
        float inv = 1.0f / Lrow[row];
        size_t base = (batchoff + qt * 64 + row) * DD + headoff + tx * 8;
#pragma unroll
        for (int j = 0; j < 8; j++) O[base + j] = Oacc[i][j] * inv;
    }
}

// ---------------- launch ----------------
extern "C" void kernel_launch(void* const* d_in, const int* in_sizes, int n_in,
                              void* d_out, int out_size) {
    const float* x    = (const float*)d_in[0];
    const float* wfQ  = (const float*)d_in[1];
    const float* wfK  = (const float*)d_in[2];
    const float* wfV  = (const float*)d_in[3];
    const float* wrQ  = (const float*)d_in[4];
    const float* wrK  = (const float*)d_in[5];
    const float* wrV  = (const float*)d_in[6];
    const float* f_qk = (const float*)d_in[7];
    const float* f_v  = (const float*)d_in[8];
    const float* r_qk = (const float*)d_in[9];
    const float* r_v  = (const float*)d_in[10];
    const float* W_O  = (const float*)d_in[11];
    float* out = (float*)d_out;

    float *Ft, *Tqk, *Tv, *WH, *Qb, *Kb, *Vb, *At, *WOt;
    cudaGetSymbolAddress((void**)&Ft,  g_Ft);
    cudaGetSymbolAddress((void**)&Tqk, g_tqk);
    cudaGetSymbolAddress((void**)&Tv,  g_tv);
    cudaGetSymbolAddress((void**)&WH,  g_wh);
    cudaGetSymbolAddress((void**)&Qb,  g_Q);
    cudaGetSymbolAddress((void**)&Kb,  g_K);
    cudaGetSymbolAddress((void**)&Vb,  g_V);
    cudaGetSymbolAddress((void**)&At,  g_At);
    cudaGetSymbolAddress((void**)&WOt, g_WOt);

    // feature GEMMs: t = X @ Ft   (4096 x 2048, K=1024)
    dim3 gFeat(NR / 128, TOK / 128);
    transpose_f_kernel<<<(NN * DD * RR) / 256, 256>>>(f_qk, Ft);
    sgemm_kernel<<<gFeat, 256>>>(x, Ft, Tqk, TOK, NR, DD);
    transpose_f_kernel<<<(NN * DD * RR) / 256, 256>>>(f_v, Ft);
    sgemm_kernel<<<gFeat, 256>>>(x, Ft, Tv, TOK, NR, DD);

    // mix + restore GEMMs: QKV = WH @ r_flat  (4096 x 1024, K=2048)
    dim3 gRest(DD / 128, TOK / 128);
    mix_kernel<<<TOK, 128>>>(Tqk, wfQ, wrQ, WH);
    sgemm_kernel<<<gRest, 256>>>(WH, r_qk, Qb, TOK, DD, NR);
    mix_kernel<<<TOK, 128>>>(Tqk, wfK, wrK, WH);
    sgemm_kernel<<<gRest, 256>>>(WH, r_qk, Kb, TOK, DD, NR);
    mix_kernel<<<TOK, 128>>>(Tv, wfV, wrV, WH);
    sgemm_kernel<<<gRest, 256>>>(WH, r_v, Vb, TOK, DD, NR);

    // causal flash attention
    cudaFuncSetAttribute(attn_kernel, cudaFuncAttributeMaxDynamicSharedMemorySize, ATTN_SMEM);
    attn_kernel<<<dim3(SS / 64, BB * HH), 128, ATTN_SMEM>>>(Qb, Kb, Vb, At);

    // out = attn @ W_O^T
    transpose_sq_kernel<<<dim3(DD / 32, DD / 32), dim3(32, 8)>>>(W_O, WOt, DD);
    sgemm_kernel<<<gRest, 256>>>(At, WOt, out, TOK, DD, DD);
}

// round 2
// speedup vs baseline: 2.1016x; 2.1016x over previous
#include <cuda_runtime.h>
#include <cuda_bf16.h>
#include <cstdint>

// Problem constants
#define BB 2
#define SS 2048
#define DD 1024
#define RR 128
#define HH 16
#define NN 16
#define DH 64
#define TOK (BB*SS)          // 4096
#define NR (NN*RR)           // 2048

// ---------------- scratch (device globals; allocation-free) ----------------
__device__ __align__(256) float g_x32[TOK * DD];      // tf32-rounded x
__device__ __align__(256) float g_rqk[NR * DD];       // tf32-rounded r_qk
__device__ __align__(256) float g_rv [NR * DD];       // tf32-rounded r_v
__device__ __align__(256) float g_Ft[DD * NR];        // transposed feature mat (D, N*R)
__device__ __align__(256) float g_tqk[TOK * NR];      // t for f_qk (tok, n, r)
__device__ __align__(256) float g_tv [TOK * NR];      // t for f_v
__device__ __align__(256) float g_wh [TOK * NR];      // wh scratch (tf32-rounded)
__device__ __align__(256) float g_Q  [TOK * DD];
__device__ __align__(256) float g_K  [TOK * DD];
__device__ __align__(256) float g_V  [TOK * DD];
__device__ __align__(256) float g_At [TOK * DD];      // attention output (tf32-rounded)
__device__ __align__(256) float g_WOt[DD * DD];       // W_O transposed (tf32-rounded)

// ---------------- helpers ----------------
__device__ __forceinline__ float tf32r(float x) {
    uint32_t u;
    asm("cvt.rna.tf32.f32 %0, %1;" : "=r"(u) : "f"(x));
    return __uint_as_float(u);
}
__device__ __forceinline__ uint32_t f2u(float x) { return __float_as_uint(x); }
__device__ __forceinline__ uint32_t smem_u32(const void* p) {
    return (uint32_t)__cvta_generic_to_shared(p);
}
__device__ __forceinline__ void cp_async16(uint32_t dst, const void* src) {
    asm volatile("cp.async.cg.shared.global [%0], [%1], 16;\n" :: "r"(dst), "l"(src));
}
__device__ __forceinline__ void cp_commit() {
    asm volatile("cp.async.commit_group;\n");
}
template <int N>
__device__ __forceinline__ void cp_wait() {
    asm volatile("cp.async.wait_group %0;\n" :: "n"(N));
}

// ---------------- elementwise tf32 rounding pass ----------------
__global__ void to_tf32_kernel(const float* __restrict__ in, float* __restrict__ out) {
    int i = (blockIdx.x * 256 + threadIdx.x) * 4;
    float4 v = *reinterpret_cast<const float4*>(in + i);
    v.x = tf32r(v.x); v.y = tf32r(v.y); v.z = tf32r(v.z); v.w = tf32r(v.w);
    *reinterpret_cast<float4*>(out + i) = v;
}

// ---------------- transpose f: (N,D,R) -> (D, N*R), tf32-rounded ----------------
__global__ void transpose_f_kernel(const float* __restrict__ f, float* __restrict__ Ft) {
    int idx = blockIdx.x * 256 + threadIdx.x;      // over N*D*R = 2^21
    int r = idx & (RR - 1);
    int d = (idx >> 7) & (DD - 1);
    int n = idx >> 17;
    Ft[d * NR + n * RR + r] = tf32r(f[idx]);
}

// ---------------- transpose square (1024x1024), tf32-rounded ----------------
__global__ void transpose_sq_kernel(const float* __restrict__ A, float* __restrict__ At, int n) {
    __shared__ float tile[32][33];
    int x = blockIdx.x * 32 + threadIdx.x;
    int y0 = blockIdx.y * 32;
    for (int i = threadIdx.y; i < 32; i += 8)
        tile[i][threadIdx.x] = A[(size_t)(y0 + i) * n + x];
    __syncthreads();
    int x2 = blockIdx.y * 32 + threadIdx.x;
    int y2 = blockIdx.x * 32;
    for (int i = threadIdx.y; i < 32; i += 8)
        At[(size_t)(y2 + i) * n + x2] = tf32r(tile[threadIdx.x][i]);
}

// ---------------- mix: h = sum_n wf*t ; wh = wr (outer) h, tf32-rounded ----
__global__ void mix_kernel(const float* __restrict__ t,
                           const float* __restrict__ wf,
                           const float* __restrict__ wr,
                           float* __restrict__ wh) {
    int tok = blockIdx.x;
    int r = threadIdx.x;   // 0..127
    const float* tp = t + (size_t)tok * NR;
    float h = 0.f;
#pragma unroll
    for (int n = 0; n < NN; n++) h += wf[tok * NN + n] * tp[n * RR + r];
#pragma unroll
    for (int n = 0; n < NN; n++)
        wh[(size_t)tok * NR + n * RR + r] = tf32r(wr[tok * NN + n] * h);
}

// ---------------- tf32 tensor-core GEMM: C = A(MxK) @ B(KxN), row-major ----
// BM=128, BN=128, BK=32, 256 threads (8 warps, 2x4), warp tile 64x32.
// A/B must already be tf32-rounded fp32. M%128==0, N%128==0, K%32==0.
#define AP 36              // A smem pitch (floats): (row*36+k)%32 conflict-free
#define BP 136             // B smem pitch (floats): (k*136+n)%32 conflict-free
#define ASZ (128 * AP)
#define BSZ (32 * BP)
#define GEMM_SMEM ((2 * ASZ + 2 * BSZ) * 4)

__global__ __launch_bounds__(256) void mma_gemm_kernel(
        const float* __restrict__ A, const float* __restrict__ B,
        float* __restrict__ C, int M, int N, int K) {
    extern __shared__ float sm[];
    float* As = sm;                 // [2][128][AP]
    float* Bs = sm + 2 * ASZ;       // [2][32][BP]

    const int tid = threadIdx.x;
    const int lane = tid & 31;
    const int wid = tid >> 5;
    const int wm = wid >> 2;        // 0..1
    const int wn = wid & 3;         // 0..3
    const int g = lane >> 2;        // 0..7
    const int tg = lane & 3;        // 0..3
    const int brow = blockIdx.y * 128;
    const int bcol = blockIdx.x * 128;

    float acc[4][4][4];
#pragma unroll
    for (int mi = 0; mi < 4; mi++)
#pragma unroll
        for (int ni = 0; ni < 4; ni++)
#pragma unroll
            for (int c = 0; c < 4; c++) acc[mi][ni][c] = 0.f;

    const int T = K >> 5;           // number of BK=32 tiles

    // tile loader (cp.async): 4 f4 of A + 4 f4 of B per thread
    auto load_tile = [&](int kt, int buf) {
        float* Ad = As + buf * ASZ;
        float* Bd = Bs + buf * BSZ;
        const int k0 = kt * 32;
#pragma unroll
        for (int l = 0; l < 4; ++l) {
            int i = tid + l * 256;          // 0..1023
            int row = i >> 3;               // 0..127
            int c4 = (i & 7) * 4;           // 0..28
            cp_async16(smem_u32(Ad + row * AP + c4),
                       A + (size_t)(brow + row) * K + k0 + c4);
        }
#pragma unroll
        for (int l = 0; l < 4; ++l) {
            int i = tid + l * 256;
            int row = i >> 5;               // 0..31
            int c4 = (i & 31) * 4;          // 0..124
            cp_async16(smem_u32(Bd + row * BP + c4),
                       B + (size_t)(k0 + row) * N + bcol + c4);
        }
        cp_commit();
    };

    load_tile(0, 0);
    int buf = 0;
    for (int kt = 0; kt < T; ++kt) {
        if (kt + 1 < T) {
            load_tile(kt + 1, buf ^ 1);
            cp_wait<1>();
        } else {
            cp_wait<0>();
        }
        __syncthreads();

        const float* Ab = As + buf * ASZ;
        const float* Bb = Bs + buf * BSZ;
#pragma unroll
        for (int ks = 0; ks < 4; ++ks) {
            const int k = ks * 8;
            uint32_t a[4][4];
#pragma unroll
            for (int mi = 0; mi < 4; mi++) {
                int row = wm * 64 + mi * 16 + g;
                a[mi][0] = f2u(Ab[row * AP + k + tg]);
                a[mi][1] = f2u(Ab[(row + 8) * AP + k + tg]);
                a[mi][2] = f2u(Ab[row * AP + k + tg + 4]);
                a[mi][3] = f2u(Ab[(row + 8) * AP + k + tg + 4]);
            }
            uint32_t b[4][2];
#pragma unroll
            for (int ni = 0; ni < 4; ni++) {
                int col = wn * 32 + ni * 8 + g;
                b[ni][0] = f2u(Bb[(k + tg) * BP + col]);
                b[ni][1] = f2u(Bb[(k + tg + 4) * BP + col]);
            }
#pragma unroll
            for (int mi = 0; mi < 4; mi++)
#pragma unroll
                for (int ni = 0; ni < 4; ni++) {
                    asm volatile(
                        "mma.sync.aligned.m16n8k8.row.col.f32.tf32.tf32.f32 "
                        "{%0,%1,%2,%3}, {%4,%5,%6,%7}, {%8,%9}, {%0,%1,%2,%3};\n"
                        : "+f"(acc[mi][ni][0]), "+f"(acc[mi][ni][1]),
                          "+f"(acc[mi][ni][2]), "+f"(acc[mi][ni][3])
                        : "r"(a[mi][0]), "r"(a[mi][1]), "r"(a[mi][2]), "r"(a[mi][3]),
                          "r"(b[ni][0]), "r"(b[ni][1]));
                }
        }
        __syncthreads();
        buf ^= 1;
    }

    // epilogue
#pragma unroll
    for (int mi = 0; mi < 4; mi++) {
#pragma unroll
        for (int ni = 0; ni < 4; ni++) {
            int row = brow + wm * 64 + mi * 16 + g;
            int col = bcol + wn * 32 + ni * 8 + tg * 2;
            *reinterpret_cast<float2*>(&C[(size_t)row * N + col]) =
                make_float2(acc[mi][ni][0], acc[mi][ni][1]);
            *reinterpret_cast<float2*>(&C[(size_t)(row + 8) * N + col]) =
                make_float2(acc[mi][ni][2], acc[mi][ni][3]);
        }
    }
}

// ---------------- causal flash attention (fp32) ----------------
// Q/K/V: (TOK, D) with head h occupying cols [h*64, h*64+64). Out same layout.
#define ATTN_SMEM ((4 * 64 * 65 + 3 * 64) * 4)
__global__ __launch_bounds__(128) void attn_kernel(
        const float* __restrict__ Q, const float* __restrict__ K,
        const float* __restrict__ V, float* __restrict__ O) {
    extern __shared__ float sm[];
    float* Qs = sm;                    // [64][65]
    float* Ks = Qs + 64 * 65;          // [64][65]
    float* Vs = Ks + 64 * 65;          // [64][65]
    float* Ps = Vs + 64 * 65;          // [64][65]
    float* Mrow = Ps + 64 * 65;        // [64]
    float* Lrow = Mrow + 64;           // [64]
    float* Arow = Lrow + 64;           // [64]

    const int qt = blockIdx.x;         // query tile 0..31
    const int bh = blockIdx.y;         // 0..31
    const int b = bh >> 4;
    const int h = bh & 15;
    const int tid = threadIdx.x;
    const int tx = tid & 7;            // 8 col-groups
    const int ty = tid >> 3;           // 16 row-groups (4 rows each)
    const float scale = 0.125f;        // 1/sqrt(64)

    const size_t headoff = (size_t)h * DH;
    const size_t batchoff = (size_t)b * SS;

    for (int i = tid; i < 64 * 64; i += 128) {
        int m = i >> 6, k = i & 63;
        Qs[m * 65 + k] = Q[(batchoff + qt * 64 + m) * DD + headoff + k];
    }
    for (int m = tid; m < 64; m += 128) { Mrow[m] = -1e30f; Lrow[m] = 0.f; }

    float Oacc[4][8];
#pragma unroll
    for (int i = 0; i < 4; i++)
#pragma unroll
        for (int j = 0; j < 8; j++) Oacc[i][j] = 0.f;
    __syncthreads();

    for (int jt = 0; jt <= qt; ++jt) {
        for (int i = tid; i < 64 * 64; i += 128) {
            int n = i >> 6, k = i & 63;
            size_t src = (batchoff + jt * 64 + n) * DD + headoff + k;
            Ks[n * 65 + k] = K[src];
            Vs[n * 65 + k] = V[src];
        }
        __syncthreads();

        float s[4][8];
#pragma unroll
        for (int i = 0; i < 4; i++)
#pragma unroll
            for (int j = 0; j < 8; j++) s[i][j] = 0.f;
        for (int k = 0; k < 64; ++k) {
            float qv[4], kv[8];
#pragma unroll
            for (int i = 0; i < 4; i++) qv[i] = Qs[(ty * 4 + i) * 65 + k];
#pragma unroll
            for (int j = 0; j < 8; j++) kv[j] = Ks[(tx * 8 + j) * 65 + k];
#pragma unroll
            for (int i = 0; i < 4; i++)
#pragma unroll
                for (int j = 0; j < 8; j++) s[i][j] += qv[i] * kv[j];
        }
#pragma unroll
        for (int i = 0; i < 4; i++)
#pragma unroll
            for (int j = 0; j < 8; j++) {
                s[i][j] *= scale;
                if (jt == qt && (tx * 8 + j) > (ty * 4 + i)) s[i][j] = -1e30f;
            }
        float rmax[4];
#pragma unroll
        for (int i = 0; i < 4; i++) {
            float m = s[i][0];
#pragma unroll
            for (int j = 1; j < 8; j++) m = fmaxf(m, s[i][j]);
            m = fmaxf(m, __shfl_xor_sync(0xffffffffu, m, 1));
            m = fmaxf(m, __shfl_xor_sync(0xffffffffu, m, 2));
            m = fmaxf(m, __shfl_xor_sync(0xffffffffu, m, 4));
            rmax[i] = m;
        }
#pragma unroll
        for (int i = 0; i < 4; i++) {
            int row = ty * 4 + i;
            float mnew = fmaxf(Mrow[row], rmax[i]);
            float ssum = 0.f;
#pragma unroll
            for (int j = 0; j < 8; j++) {
                float p = __expf(s[i][j] - mnew);
                Ps[row * 65 + tx * 8 + j] = p;
                ssum += p;
            }
            ssum += __shfl_xor_sync(0xffffffffu, ssum, 1);
            ssum += __shfl_xor_sync(0xffffffffu, ssum, 2);
            ssum += __shfl_xor_sync(0xffffffffu, ssum, 4);
            if (tx == 0) {
                float alpha = __expf(Mrow[row] - mnew);
                Arow[row] = alpha;
                Lrow[row] = Lrow[row] * alpha + ssum;
                Mrow[row] = mnew;
            }
        }
        __syncthreads();

        float a[4];
#pragma unroll
        for (int i = 0; i < 4; i++) a[i] = Arow[ty * 4 + i];
#pragma unroll
        for (int i = 0; i < 4; i++)
#pragma unroll
            for (int j = 0; j < 8; j++) Oacc[i][j] *= a[i];
        for (int n = 0; n < 64; ++n) {
            float pv[4], vv[8];
#pragma unroll
            for (int i = 0; i < 4; i++) pv[i] = Ps[(ty * 4 + i) * 65 + n];
#pragma unroll
            for (int j = 0; j < 8; j++) vv[j] = Vs[n * 65 + tx * 8 + j];
#pragma unroll
            for (int i = 0; i < 4; i++)
#pragma unroll
                for (int j = 0; j < 8; j++) Oacc[i][j] += pv[i] * vv[j];
        }
        __syncthreads();
    }

    // epilogue: divide by L, tf32-round (feeds the output GEMM), write (tok, D)
#pragma unroll
    for (int i = 0; i < 4; i++) {
        int row = ty * 4 + i;
        float inv = 1.0f / Lrow[row];
        size_t base = (batchoff + qt * 64 + row) * DD + headoff + tx * 8;
#pragma unroll
        for (int j = 0; j < 8; j++) O[base + j] = tf32r(Oacc[i][j] * inv);
    }
}

// ---------------- launch ----------------
extern "C" void kernel_launch(void* const* d_in, const int* in_sizes, int n_in,
                              void* d_out, int out_size) {
    const float* x    = (const float*)d_in[0];
    const float* wfQ  = (const float*)d_in[1];
    const float* wfK  = (const float*)d_in[2];
    const float* wfV  = (const float*)d_in[3];
    const float* wrQ  = (const float*)d_in[4];
    const float* wrK  = (const float*)d_in[5];
    const float* wrV  = (const float*)d_in[6];
    const float* f_qk = (const float*)d_in[7];
    const float* f_v  = (const float*)d_in[8];
    const float* r_qk = (const float*)d_in[9];
    const float* r_v  = (const float*)d_in[10];
    const float* W_O  = (const float*)d_in[11];
    float* out = (float*)d_out;

    float *X32, *Rqk, *Rv, *Ft, *Tqk, *Tv, *WH, *Qb, *Kb, *Vb, *At, *WOt;
    cudaGetSymbolAddress((void**)&X32, g_x32);
    cudaGetSymbolAddress((void**)&Rqk, g_rqk);
    cudaGetSymbolAddress((void**)&Rv,  g_rv);
    cudaGetSymbolAddress((void**)&Ft,  g_Ft);
    cudaGetSymbolAddress((void**)&Tqk, g_tqk);
    cudaGetSymbolAddress((void**)&Tv,  g_tv);
    cudaGetSymbolAddress((void**)&WH,  g_wh);
    cudaGetSymbolAddress((void**)&Qb,  g_Q);
    cudaGetSymbolAddress((void**)&Kb,  g_K);
    cudaGetSymbolAddress((void**)&Vb,  g_V);
    cudaGetSymbolAddress((void**)&At,  g_At);
    cudaGetSymbolAddress((void**)&WOt, g_WOt);

    cudaFuncSetAttribute(mma_gemm_kernel,
                         cudaFuncAttributeMaxDynamicSharedMemorySize, GEMM_SMEM);
    cudaFuncSetAttribute(attn_kernel,
                         cudaFuncAttributeMaxDynamicSharedMemorySize, ATTN_SMEM);

    // tf32-round GEMM operands that come straight from inputs
    to_tf32_kernel<<<(TOK * DD) / 1024, 256>>>(x, X32);
    to_tf32_kernel<<<(NR * DD) / 1024, 256>>>(r_qk, Rqk);
    to_tf32_kernel<<<(NR * DD) / 1024, 256>>>(r_v, Rv);

    // feature GEMMs: t = X @ Ft   (4096 x 2048, K=1024)
    dim3 gFeat(NR / 128, TOK / 128);
    transpose_f_kernel<<<(NN * DD * RR) / 256, 256>>>(f_qk, Ft);
    mma_gemm_kernel<<<gFeat, 256, GEMM_SMEM>>>(X32, Ft, Tqk, TOK, NR, DD);
    transpose_f_kernel<<<(NN * DD * RR) / 256, 256>>>(f_v, Ft);
    mma_gemm_kernel<<<gFeat, 256, GEMM_SMEM>>>(X32, Ft, Tv, TOK, NR, DD);

    // mix + restore GEMMs: QKV = WH @ r_flat  (4096 x 1024, K=2048)
    dim3 gRest(DD / 128, TOK / 128);
    mix_kernel<<<TOK, 128>>>(Tqk, wfQ, wrQ, WH);
    mma_gemm_kernel<<<gRest, 256, GEMM_SMEM>>>(WH, Rqk, Qb, TOK, DD, NR);
    mix_kernel<<<TOK, 128>>>(Tqk, wfK, wrK, WH);
    mma_gemm_kernel<<<gRest, 256, GEMM_SMEM>>>(WH, Rqk, Kb, TOK, DD, NR);
    mix_kernel<<<TOK, 128>>>(Tv, wfV, wrV, WH);
    mma_gemm_kernel<<<gRest, 256, GEMM_SMEM>>>(WH, Rv, Vb, TOK, DD, NR);

    // causal flash attention
    attn_kernel<<<dim3(SS / 64, BB * HH), 128, ATTN_SMEM>>>(Qb, Kb, Vb, At);

    // out = attn @ W_O^T
    transpose_sq_kernel<<<dim3(DD / 32, DD / 32), dim3(32, 8)>>>(W_O, WOt, DD);
    mma_gemm_kernel<<<gRest, 256, GEMM_SMEM>>>(At, WOt, out, TOK, DD, DD);
}

// round 5
// speedup vs baseline: 3.6412x; 1.7326x over previous
#include <cuda_runtime.h>
#include <cuda_bf16.h>
#include <cstdint>

// Problem constants
#define BB 2
#define SS 2048
#define DD 1024
#define RR 128
#define HH 16
#define NN 16
#define DH 64
#define TOK (BB*SS)          // 4096
#define NR (NN*RR)           // 2048

// ---------------- scratch (device globals; allocation-free) ----------------
__device__ __align__(256) float g_x32[TOK * DD];      // tf32-rounded x
__device__ __align__(256) float g_rqk[NR * DD];       // tf32-rounded r_qk
__device__ __align__(256) float g_rv [NR * DD];       // tf32-rounded r_v
__device__ __align__(256) float g_Ft[DD * NR];        // transposed feature mat (D, N*R)
__device__ __align__(256) float g_tqk[TOK * NR];      // t for f_qk (tok, n, r)
__device__ __align__(256) float g_tv [TOK * NR];      // t for f_v
__device__ __align__(256) float g_wh [TOK * NR];      // wh scratch (tf32-rounded)
__device__ __align__(256) float g_Q  [TOK * DD];
__device__ __align__(256) float g_K  [TOK * DD];
__device__ __align__(256) float g_V  [TOK * DD];
__device__ __align__(256) float g_At [TOK * DD];      // attention output (tf32-rounded)
__device__ __align__(256) float g_WOt[DD * DD];       // W_O transposed (tf32-rounded)

// ---------------- helpers ----------------
__device__ __forceinline__ float tf32r(float x) {
    uint32_t u;
    asm("cvt.rna.tf32.f32 %0, %1;" : "=r"(u) : "f"(x));
    return __uint_as_float(u);
}
__device__ __forceinline__ uint32_t f2u(float x) { return __float_as_uint(x); }
__device__ __forceinline__ uint32_t smem_u32(const void* p) {
    return (uint32_t)__cvta_generic_to_shared(p);
}
__device__ __forceinline__ void cp_async16(uint32_t dst, const void* src) {
    asm volatile("cp.async.cg.shared.global [%0], [%1], 16;\n" :: "r"(dst), "l"(src));
}
__device__ __forceinline__ void cp_commit() {
    asm volatile("cp.async.commit_group;\n");
}
template <int N>
__device__ __forceinline__ void cp_wait() {
    asm volatile("cp.async.wait_group %0;\n" :: "n"(N));
}
// one m16n8k8 tf32 mma
__device__ __forceinline__ void mma_tf32(float* c, const uint32_t a[4],
                                         uint32_t b0, uint32_t b1) {
    asm volatile(
        "mma.sync.aligned.m16n8k8.row.col.f32.tf32.tf32.f32 "
        "{%0,%1,%2,%3}, {%4,%5,%6,%7}, {%8,%9}, {%0,%1,%2,%3};\n"
        : "+f"(c[0]), "+f"(c[1]), "+f"(c[2]), "+f"(c[3])
        : "r"(a[0]), "r"(a[1]), "r"(a[2]), "r"(a[3]), "r"(b0), "r"(b1));
}

// ---------------- elementwise tf32 rounding pass ----------------
__global__ void to_tf32_kernel(const float* __restrict__ in, float* __restrict__ out) {
    int i = (blockIdx.x * 256 + threadIdx.x) * 4;
    float4 v = *reinterpret_cast<const float4*>(in + i);
    v.x = tf32r(v.x); v.y = tf32r(v.y); v.z = tf32r(v.z); v.w = tf32r(v.w);
    *reinterpret_cast<float4*>(out + i) = v;
}

// ---------------- transpose f: (N,D,R) -> (D, N*R), tf32-rounded ----------------
__global__ void transpose_f_kernel(const float* __restrict__ f, float* __restrict__ Ft) {
    int idx = blockIdx.x * 256 + threadIdx.x;      // over N*D*R = 2^21
    int r = idx & (RR - 1);
    int d = (idx >> 7) & (DD - 1);
    int n = idx >> 17;
    Ft[d * NR + n * RR + r] = tf32r(f[idx]);
}

// ---------------- transpose square (1024x1024), tf32-rounded ----------------
__global__ void transpose_sq_kernel(const float* __restrict__ A, float* __restrict__ At, int n) {
    __shared__ float tile[32][33];
    int x = blockIdx.x * 32 + threadIdx.x;
    int y0 = blockIdx.y * 32;
    for (int i = threadIdx.y; i < 32; i += 8)
        tile[i][threadIdx.x] = A[(size_t)(y0 + i) * n + x];
    __syncthreads();
    int x2 = blockIdx.y * 32 + threadIdx.x;
    int y2 = blockIdx.x * 32;
    for (int i = threadIdx.y; i < 32; i += 8)
        At[(size_t)(y2 + i) * n + x2] = tf32r(tile[threadIdx.x][i]);
}

// ---------------- mix: h = sum_n wf*t ; wh = wr (outer) h, tf32-rounded ----
__global__ void mix_kernel(const float* __restrict__ t,
                           const float* __restrict__ wf,
                           const float* __restrict__ wr,
                           float* __restrict__ wh) {
    int tok = blockIdx.x;
    int r = threadIdx.x;   // 0..127
    const float* tp = t + (size_t)tok * NR;
    float h = 0.f;
#pragma unroll
    for (int n = 0; n < NN; n++) h += wf[tok * NN + n] * tp[n * RR + r];
#pragma unroll
    for (int n = 0; n < NN; n++)
        wh[(size_t)tok * NR + n * RR + r] = tf32r(wr[tok * NN + n] * h);
}

// ---------------- tf32 tensor-core GEMM: C = A(MxK) @ B(KxN), row-major ----
// BM=128, BN=128, BK=32, 256 threads (8 warps, 2x4), warp tile 64x32.
#define AP 36              // A smem pitch
#define BP 136             // B smem pitch
#define ASZ (128 * AP)
#define BSZ (32 * BP)
#define GEMM_SMEM ((2 * ASZ + 2 * BSZ) * 4)

__global__ __launch_bounds__(256) void mma_gemm_kernel(
        const float* __restrict__ A, const float* __restrict__ B,
        float* __restrict__ C, int M, int N, int K) {
    extern __shared__ float sm[];
    float* As = sm;                 // [2][128][AP]
    float* Bs = sm + 2 * ASZ;       // [2][32][BP]

    const int tid = threadIdx.x;
    const int lane = tid & 31;
    const int wid = tid >> 5;
    const int wm = wid >> 2;        // 0..1
    const int wn = wid & 3;         // 0..3
    const int g = lane >> 2;        // 0..7
    const int tg = lane & 3;        // 0..3
    const int brow = blockIdx.y * 128;
    const int bcol = blockIdx.x * 128;

    float acc[4][4][4];
#pragma unroll
    for (int mi = 0; mi < 4; mi++)
#pragma unroll
        for (int ni = 0; ni < 4; ni++)
#pragma unroll
            for (int c = 0; c < 4; c++) acc[mi][ni][c] = 0.f;

    const int T = K >> 5;

    auto load_tile = [&](int kt, int buf) {
        float* Ad = As + buf * ASZ;
        float* Bd = Bs + buf * BSZ;
        const int k0 = kt * 32;
#pragma unroll
        for (int l = 0; l < 4; ++l) {
            int i = tid + l * 256;
            int row = i >> 3;
            int c4 = (i & 7) * 4;
            cp_async16(smem_u32(Ad + row * AP + c4),
                       A + (size_t)(brow + row) * K + k0 + c4);
        }
#pragma unroll
        for (int l = 0; l < 4; ++l) {
            int i = tid + l * 256;
            int row = i >> 5;
            int c4 = (i & 31) * 4;
            cp_async16(smem_u32(Bd + row * BP + c4),
                       B + (size_t)(k0 + row) * N + bcol + c4);
        }
        cp_commit();
    };

    load_tile(0, 0);
    int buf = 0;
    for (int kt = 0; kt < T; ++kt) {
        if (kt + 1 < T) {
            load_tile(kt + 1, buf ^ 1);
            cp_wait<1>();
        } else {
            cp_wait<0>();
        }
        __syncthreads();

        const float* Ab = As + buf * ASZ;
        const float* Bb = Bs + buf * BSZ;
#pragma unroll
        for (int ks = 0; ks < 4; ++ks) {
            const int k = ks * 8;
            uint32_t a[4][4];
#pragma unroll
            for (int mi = 0; mi < 4; mi++) {
                int row = wm * 64 + mi * 16 + g;
                a[mi][0] = f2u(Ab[row * AP + k + tg]);
                a[mi][1] = f2u(Ab[(row + 8) * AP + k + tg]);
                a[mi][2] = f2u(Ab[row * AP + k + tg + 4]);
                a[mi][3] = f2u(Ab[(row + 8) * AP + k + tg + 4]);
            }
            uint32_t b[4][2];
#pragma unroll
            for (int ni = 0; ni < 4; ni++) {
                int col = wn * 32 + ni * 8 + g;
                b[ni][0] = f2u(Bb[(k + tg) * BP + col]);
                b[ni][1] = f2u(Bb[(k + tg + 4) * BP + col]);
            }
#pragma unroll
            for (int mi = 0; mi < 4; mi++)
#pragma unroll
                for (int ni = 0; ni < 4; ni++)
                    mma_tf32(acc[mi][ni], a[mi], b[ni][0], b[ni][1]);
        }
        __syncthreads();
        buf ^= 1;
    }

#pragma unroll
    for (int mi = 0; mi < 4; mi++) {
#pragma unroll
        for (int ni = 0; ni < 4; ni++) {
            int row = brow + wm * 64 + mi * 16 + g;
            int col = bcol + wn * 32 + ni * 8 + tg * 2;
            *reinterpret_cast<float2*>(&C[(size_t)row * N + col]) =
                make_float2(acc[mi][ni][0], acc[mi][ni][1]);
            *reinterpret_cast<float2*>(&C[(size_t)(row + 8) * N + col]) =
                make_float2(acc[mi][ni][2], acc[mi][ni][3]);
        }
    }
}

// ---------------- causal flash attention (tf32 mma.sync) -------------------
// Q/K/V: (TOK, D), head h at cols [h*64, h*64+64). 64x64 Q tile per CTA,
// 4 warps x 16 rows. Softmax stats in registers; P via per-warp smem tile.
#define AT_PA 68           // pitch for Qs/Ks/Ps (banks 4g+tg unique)
#define AT_PV 72           // pitch for Vs (banks 8tg+g unique)
#define ATTN_SMEM ((3 * 64 * AT_PA + 64 * AT_PV) * 4)

__global__ __launch_bounds__(128) void attn_mma_kernel(
        const float* __restrict__ Q, const float* __restrict__ K,
        const float* __restrict__ V, float* __restrict__ O) {
    extern __shared__ float sm[];
    float* Qs = sm;                      // [64][AT_PA]
    float* Ks = Qs + 64 * AT_PA;         // [64][AT_PA]
    float* Ps = Ks + 64 * AT_PA;         // [64][AT_PA]
    float* Vs = Ps + 64 * AT_PA;         // [64][AT_PV]

    const int qt = blockIdx.x;           // 0..31
    const int bh = blockIdx.y;           // 0..31
    const int b = bh >> 4;
    const int h = bh & 15;
    const int tid = threadIdx.x;
    const int wid = tid >> 5;
    const int lane = tid & 31;
    const int g = lane >> 2;             // 0..7
    const int tg = lane & 3;             // 0..3
    const int mrow = wid * 16;           // warp's row base in tile

    const size_t headoff = (size_t)h * DH;
    const size_t batchoff = (size_t)b * SS;

    // ---- load Q tile (scaled by 1/8, tf32-rounded) ----
    for (int i = tid; i < 64 * 16; i += 128) {
        int m = i >> 4;
        int c4 = (i & 15) * 4;
        float4 v = *reinterpret_cast<const float4*>(
            &Q[(batchoff + qt * 64 + m) * DD + headoff + c4]);
        v.x = tf32r(v.x * 0.125f); v.y = tf32r(v.y * 0.125f);
        v.z = tf32r(v.z * 0.125f); v.w = tf32r(v.w * 0.125f);
        *reinterpret_cast<float4*>(&Qs[m * AT_PA + c4]) = v;
    }
    __syncthreads();

    // preload Q fragments for this warp's 16 rows (8 k-tiles)
    uint32_t qa[8][4];
#pragma unroll
    for (int kk = 0; kk < 8; ++kk) {
        int k = kk * 8;
        qa[kk][0] = f2u(Qs[(mrow + g) * AT_PA + k + tg]);
        qa[kk][1] = f2u(Qs[(mrow + g + 8) * AT_PA + k + tg]);
        qa[kk][2] = f2u(Qs[(mrow + g) * AT_PA + k + tg + 4]);
        qa[kk][3] = f2u(Qs[(mrow + g + 8) * AT_PA + k + tg + 4]);
    }

    float oacc[8][4];
#pragma unroll
    for (int j = 0; j < 8; j++)
#pragma unroll
        for (int c = 0; c < 4; c++) oacc[j][c] = 0.f;
    float m0 = -1e30f, m1 = -1e30f, l0 = 0.f, l1 = 0.f;

    for (int jt = 0; jt <= qt; ++jt) {
        // ---- load K/V tile (tf32-rounded) ----
        for (int i = tid; i < 64 * 16; i += 128) {
            int m = i >> 4;
            int c4 = (i & 15) * 4;
            size_t src = (batchoff + jt * 64 + m) * DD + headoff + c4;
            float4 kv = *reinterpret_cast<const float4*>(&K[src]);
            kv.x = tf32r(kv.x); kv.y = tf32r(kv.y);
            kv.z = tf32r(kv.z); kv.w = tf32r(kv.w);
            *reinterpret_cast<float4*>(&Ks[m * AT_PA + c4]) = kv;
            float4 vv = *reinterpret_cast<const float4*>(&V[src]);
            vv.x = tf32r(vv.x); vv.y = tf32r(vv.y);
            vv.z = tf32r(vv.z); vv.w = tf32r(vv.w);
            *reinterpret_cast<float4*>(&Vs[m * AT_PV + c4]) = vv;
        }
        __syncthreads();

        // ---- scores: S = Qs @ Ks^T  (8 n-tiles of 8 key cols) ----
        float sacc[8][4];
#pragma unroll
        for (int j = 0; j < 8; j++)
#pragma unroll
            for (int c = 0; c < 4; c++) sacc[j][c] = 0.f;
#pragma unroll
        for (int kk = 0; kk < 8; ++kk) {
            int k = kk * 8;
            uint32_t b0[8], b1[8];
#pragma unroll
            for (int j = 0; j < 8; j++) {
                b0[j] = f2u(Ks[(j * 8 + g) * AT_PA + k + tg]);
                b1[j] = f2u(Ks[(j * 8 + g) * AT_PA + k + tg + 4]);
            }
#pragma unroll
            for (int j = 0; j < 8; j++)
                mma_tf32(sacc[j], qa[kk], b0[j], b1[j]);
        }

        // ---- causal mask on diagonal tile ----
        if (jt == qt) {
#pragma unroll
            for (int j = 0; j < 8; j++)
#pragma unroll
                for (int c = 0; c < 2; c++) {
                    int col = j * 8 + tg * 2 + c;
                    if (col > mrow + g) sacc[j][c] = -1e30f;
                    if (col > mrow + g + 8) sacc[j][2 + c] = -1e30f;
                }
        }

        // ---- online softmax (stats in registers, rows g and g+8) ----
        float vm0 = -1e30f, vm1 = -1e30f;
#pragma unroll
        for (int j = 0; j < 8; j++) {
            vm0 = fmaxf(vm0, fmaxf(sacc[j][0], sacc[j][1]));
            vm1 = fmaxf(vm1, fmaxf(sacc[j][2], sacc[j][3]));
        }
        vm0 = fmaxf(vm0, __shfl_xor_sync(0xffffffffu, vm0, 1));
        vm0 = fmaxf(vm0, __shfl_xor_sync(0xffffffffu, vm0, 2));
        vm1 = fmaxf(vm1, __shfl_xor_sync(0xffffffffu, vm1, 1));
        vm1 = fmaxf(vm1, __shfl_xor_sync(0xffffffffu, vm1, 2));
        float mn0 = fmaxf(m0, vm0);
        float mn1 = fmaxf(m1, vm1);
        float a0 = __expf(m0 - mn0);
        float a1 = __expf(m1 - mn1);
        float s0 = 0.f, s1 = 0.f;
#pragma unroll
        for (int j = 0; j < 8; j++) {
            int col = j * 8 + tg * 2;
            float p00 = __expf(sacc[j][0] - mn0);
            float p01 = __expf(sacc[j][1] - mn0);
            float p10 = __expf(sacc[j][2] - mn1);
            float p11 = __expf(sacc[j][3] - mn1);
            s0 += p00 + p01;
            s1 += p10 + p11;
            Ps[(mrow + g) * AT_PA + col] = tf32r(p00);
            Ps[(mrow + g) * AT_PA + col + 1] = tf32r(p01);
            Ps[(mrow + g + 8) * AT_PA + col] = tf32r(p10);
            Ps[(mrow + g + 8) * AT_PA + col + 1] = tf32r(p11);
        }
        s0 += __shfl_xor_sync(0xffffffffu, s0, 1);
        s0 += __shfl_xor_sync(0xffffffffu, s0, 2);
        s1 += __shfl_xor_sync(0xffffffffu, s1, 1);
        s1 += __shfl_xor_sync(0xffffffffu, s1, 2);
        l0 = l0 * a0 + s0;
        l1 = l1 * a1 + s1;
        m0 = mn0; m1 = mn1;
#pragma unroll
        for (int j = 0; j < 8; j++) {
            oacc[j][0] *= a0; oacc[j][1] *= a0;
            oacc[j][2] *= a1; oacc[j][3] *= a1;
        }
        __syncwarp();

        // ---- O += P @ V  (8 dh-tiles) ----
#pragma unroll
        for (int kk = 0; kk < 8; ++kk) {
            int k = kk * 8;
            uint32_t pa[4];
            pa[0] = f2u(Ps[(mrow + g) * AT_PA + k + tg]);
            pa[1] = f2u(Ps[(mrow + g + 8) * AT_PA + k + tg]);
            pa[2] = f2u(Ps[(mrow + g) * AT_PA + k + tg + 4]);
            pa[3] = f2u(Ps[(mrow + g + 8) * AT_PA + k + tg + 4]);
#pragma unroll
            for (int j = 0; j < 8; j++) {
                uint32_t vb0 = f2u(Vs[(k + tg) * AT_PV + j * 8 + g]);
                uint32_t vb1 = f2u(Vs[(k + tg + 4) * AT_PV + j * 8 + g]);
                mma_tf32(oacc[j], pa, vb0, vb1);
            }
        }
        __syncthreads();   // before next iteration overwrites Ks/Vs
    }

    // ---- epilogue: /L, tf32-round (feeds output GEMM) ----
    float inv0 = 1.0f / l0;
    float inv1 = 1.0f / l1;
    size_t row0 = (batchoff + qt * 64 + mrow + g) * DD + headoff;
    size_t row1 = row0 + 8 * DD;
#pragma unroll
    for (int j = 0; j < 8; j++) {
        int col = j * 8 + tg * 2;
        O[row0 + col] = tf32r(oacc[j][0] * inv0);
        O[row0 + col + 1] = tf32r(oacc[j][1] * inv0);
        O[row1 + col] = tf32r(oacc[j][2] * inv1);
        O[row1 + col + 1] = tf32r(oacc[j][3] * inv1);
    }
}

// ---------------- launch ----------------
extern "C" void kernel_launch(void* const* d_in, const int* in_sizes, int n_in,
                              void* d_out, int out_size) {
    const float* x    = (const float*)d_in[0];
    const float* wfQ  = (const float*)d_in[1];
    const float* wfK  = (const float*)d_in[2];
    const float* wfV  = (const float*)d_in[3];
    const float* wrQ  = (const float*)d_in[4];
    const float* wrK  = (const float*)d_in[5];
    const float* wrV  = (const float*)d_in[6];
    const float* f_qk = (const float*)d_in[7];
    const float* f_v  = (const float*)d_in[8];
    const float* r_qk = (const float*)d_in[9];
    const float* r_v  = (const float*)d_in[10];
    const float* W_O  = (const float*)d_in[11];
    float* out = (float*)d_out;

    float *X32, *Rqk, *Rv, *Ft, *Tqk, *Tv, *WH, *Qb, *Kb, *Vb, *At, *WOt;
    cudaGetSymbolAddress((void**)&X32, g_x32);
    cudaGetSymbolAddress((void**)&Rqk, g_rqk);
    cudaGetSymbolAddress((void**)&Rv,  g_rv);
    cudaGetSymbolAddress((void**)&Ft,  g_Ft);
    cudaGetSymbolAddress((void**)&Tqk, g_tqk);
    cudaGetSymbolAddress((void**)&Tv,  g_tv);
    cudaGetSymbolAddress((void**)&WH,  g_wh);
    cudaGetSymbolAddress((void**)&Qb,  g_Q);
    cudaGetSymbolAddress((void**)&Kb,  g_K);
    cudaGetSymbolAddress((void**)&Vb,  g_V);
    cudaGetSymbolAddress((void**)&At,  g_At);
    cudaGetSymbolAddress((void**)&WOt, g_WOt);

    cudaFuncSetAttribute(mma_gemm_kernel,
                         cudaFuncAttributeMaxDynamicSharedMemorySize, GEMM_SMEM);
    cudaFuncSetAttribute(attn_mma_kernel,
                         cudaFuncAttributeMaxDynamicSharedMemorySize, ATTN_SMEM);

    // tf32-round GEMM operands from inputs
    to_tf32_kernel<<<(TOK * DD) / 1024, 256>>>(x, X32);
    to_tf32_kernel<<<(NR * DD) / 1024, 256>>>(r_qk, Rqk);
    to_tf32_kernel<<<(NR * DD) / 1024, 256>>>(r_v, Rv);

    // feature GEMMs: t = X @ Ft   (4096 x 2048, K=1024)
    dim3 gFeat(NR / 128, TOK / 128);
    transpose_f_kernel<<<(NN * DD * RR) / 256, 256>>>(f_qk, Ft);
    mma_gemm_kernel<<<gFeat, 256, GEMM_SMEM>>>(X32, Ft, Tqk, TOK, NR, DD);
    transpose_f_kernel<<<(NN * DD * RR) / 256, 256>>>(f_v, Ft);
    mma_gemm_kernel<<<gFeat, 256, GEMM_SMEM>>>(X32, Ft, Tv, TOK, NR, DD);

    // mix + restore GEMMs: QKV = WH @ r_flat  (4096 x 1024, K=2048)
    dim3 gRest(DD / 128, TOK / 128);
    mix_kernel<<<TOK, 128>>>(Tqk, wfQ, wrQ, WH);
    mma_gemm_kernel<<<gRest, 256, GEMM_SMEM>>>(WH, Rqk, Qb, TOK, DD, NR);
    mix_kernel<<<TOK, 128>>>(Tqk, wfK, wrK, WH);
    mma_gemm_kernel<<<gRest, 256, GEMM_SMEM>>>(WH, Rqk, Kb, TOK, DD, NR);
    mix_kernel<<<TOK, 128>>>(Tv, wfV, wrV, WH);
    mma_gemm_kernel<<<gRest, 256, GEMM_SMEM>>>(WH, Rv, Vb, TOK, DD, NR);

    // causal flash attention (tensor cores)
    attn_mma_kernel<<<dim3(SS / 64, BB * HH), 128, ATTN_SMEM>>>(Qb, Kb, Vb, At);

    // out = attn @ W_O^T
    transpose_sq_kernel<<<dim3(DD / 32, DD / 32), dim3(32, 8)>>>(W_O, WOt, DD);
    mma_gemm_kernel<<<gRest, 256, GEMM_SMEM>>>(At, WOt, out, TOK, DD, DD);
}

// round 6
// speedup vs baseline: 3.8108x; 1.0466x over previous
#include <cuda_runtime.h>
#include <cuda_bf16.h>
#include <cstdint>

// Problem constants
#define BB 2
#define SS 2048
#define DD 1024
#define RR 128
#define HH 16
#define NN 16
#define DH 64
#define TOK (BB*SS)          // 4096
#define NR (NN*RR)           // 2048

// ---------------- scratch (device globals; allocation-free) ----------------
__device__ __align__(256) float g_x32[TOK * DD];       // tf32-rounded x
__device__ __align__(256) float g_rqk[NR * DD];        // tf32-rounded r_qk
__device__ __align__(256) float g_rv [NR * DD];        // tf32-rounded r_v
__device__ __align__(256) float g_Ft [DD * 2 * NR];    // [D][4096]: cols 0..2047 f_qk^T, 2048.. f_v^T
__device__ __align__(256) float g_t  [TOK * 2 * NR];   // [tok][4096]: tqk | tv
__device__ __align__(256) float g_wh [2 * TOK * NR];   // [2*tok][NR]: wh_q rows then wh_k rows
__device__ __align__(256) float g_whv[TOK * NR];       // wh_v
__device__ __align__(256) float g_QK [2 * TOK * DD];   // Q rows then K rows
__device__ __align__(256) float g_V  [TOK * DD];
__device__ __align__(256) float g_At [TOK * DD];       // attention output (tf32-rounded)
__device__ __align__(256) float g_WOt[DD * DD];        // W_O transposed (tf32-rounded)

// ---------------- helpers ----------------
__device__ __forceinline__ float tf32r(float x) {
    uint32_t u;
    asm("cvt.rna.tf32.f32 %0, %1;" : "=r"(u) : "f"(x));
    return __uint_as_float(u);
}
__device__ __forceinline__ uint32_t f2u(float x) { return __float_as_uint(x); }
__device__ __forceinline__ uint32_t smem_u32(const void* p) {
    return (uint32_t)__cvta_generic_to_shared(p);
}
__device__ __forceinline__ void cp_async16(uint32_t dst, const void* src) {
    asm volatile("cp.async.cg.shared.global [%0], [%1], 16;\n" :: "r"(dst), "l"(src));
}
__device__ __forceinline__ void cp_commit() {
    asm volatile("cp.async.commit_group;\n");
}
template <int N>
__device__ __forceinline__ void cp_wait() {
    asm volatile("cp.async.wait_group %0;\n" :: "n"(N));
}
// one m16n8k8 tf32 mma
__device__ __forceinline__ void mma_tf32(float* c, const uint32_t a[4],
                                         uint32_t b0, uint32_t b1) {
    asm volatile(
        "mma.sync.aligned.m16n8k8.row.col.f32.tf32.tf32.f32 "
        "{%0,%1,%2,%3}, {%4,%5,%6,%7}, {%8,%9}, {%0,%1,%2,%3};\n"
        : "+f"(c[0]), "+f"(c[1]), "+f"(c[2]), "+f"(c[3])
        : "r"(a[0]), "r"(a[1]), "r"(a[2]), "r"(a[3]), "r"(b0), "r"(b1));
}

// ---------------- elementwise tf32 rounding pass ----------------
__global__ void to_tf32_kernel(const float* __restrict__ in, float* __restrict__ out) {
    int i = (blockIdx.x * 256 + threadIdx.x) * 4;
    float4 v = *reinterpret_cast<const float4*>(in + i);
    v.x = tf32r(v.x); v.y = tf32r(v.y); v.z = tf32r(v.z); v.w = tf32r(v.w);
    *reinterpret_cast<float4*>(out + i) = v;
}

// ---------------- transpose f: (N,D,R) -> Ft[d][coff + n*R + r], tf32 ------
__global__ void transpose_f_kernel(const float* __restrict__ f, float* __restrict__ Ft,
                                   int coff) {
    int idx = blockIdx.x * 256 + threadIdx.x;      // over N*D*R = 2^21
    int r = idx & (RR - 1);
    int d = (idx >> 7) & (DD - 1);
    int n = idx >> 17;
    Ft[(size_t)d * (2 * NR) + coff + n * RR + r] = tf32r(f[idx]);
}

// ---------------- transpose square (1024x1024), tf32-rounded ----------------
__global__ void transpose_sq_kernel(const float* __restrict__ A, float* __restrict__ At, int n) {
    __shared__ float tile[32][33];
    int x = blockIdx.x * 32 + threadIdx.x;
    int y0 = blockIdx.y * 32;
    for (int i = threadIdx.y; i < 32; i += 8)
        tile[i][threadIdx.x] = A[(size_t)(y0 + i) * n + x];
    __syncthreads();
    int x2 = blockIdx.y * 32 + threadIdx.x;
    int y2 = blockIdx.x * 32;
    for (int i = threadIdx.y; i < 32; i += 8)
        At[(size_t)(y2 + i) * n + x2] = tf32r(tile[threadIdx.x][i]);
}

// ---------------- mix: h = sum_n wf*t ; wh = wr (outer) h, tf32-rounded ----
// t rows have stride tstride (batched feature layout); wh rows contiguous NR.
__global__ void mix_kernel(const float* __restrict__ t,
                           const float* __restrict__ wf,
                           const float* __restrict__ wr,
                           float* __restrict__ wh, int tstride) {
    int tok = blockIdx.x;
    int r = threadIdx.x;   // 0..127
    const float* tp = t + (size_t)tok * tstride;
    float h = 0.f;
#pragma unroll
    for (int n = 0; n < NN; n++) h += wf[tok * NN + n] * tp[n * RR + r];
#pragma unroll
    for (int n = 0; n < NN; n++)
        wh[(size_t)tok * NR + n * RR + r] = tf32r(wr[tok * NN + n] * h);
}

// ---------------- tf32 tensor-core GEMM: C = A(MxK) @ B(KxN), row-major ----
// BM=128, BN=128, BK=32, 3-stage cp.async ring, ONE syncthreads per K-iter.
// 256 threads (8 warps, 2x4), warp tile 64x32.
#define AP 36              // A smem pitch
#define BP 136             // B smem pitch
#define ASZ (128 * AP)
#define BSZ (32 * BP)
#define GEMM_SMEM (3 * (ASZ + BSZ) * 4)

__global__ __launch_bounds__(256) void mma_gemm_kernel(
        const float* __restrict__ A, const float* __restrict__ B,
        float* __restrict__ C, int M, int N, int K) {
    extern __shared__ float sm[];
    float* As = sm;                 // [3][128][AP]
    float* Bs = sm + 3 * ASZ;       // [3][32][BP]

    const int tid = threadIdx.x;
    const int lane = tid & 31;
    const int wid = tid >> 5;
    const int wm = wid >> 2;        // 0..1
    const int wn = wid & 3;         // 0..3
    const int g = lane >> 2;        // 0..7
    const int tg = lane & 3;        // 0..3
    const int brow = blockIdx.y * 128;
    const int bcol = blockIdx.x * 128;

    float acc[4][4][4];
#pragma unroll
    for (int mi = 0; mi < 4; mi++)
#pragma unroll
        for (int ni = 0; ni < 4; ni++)
#pragma unroll
            for (int c = 0; c < 4; c++) acc[mi][ni][c] = 0.f;

    const int T = K >> 5;

    auto load_tile = [&](int kt, int buf) {
        float* Ad = As + buf * ASZ;
        float* Bd = Bs + buf * BSZ;
        const int k0 = kt * 32;
#pragma unroll
        for (int l = 0; l < 4; ++l) {
            int i = tid + l * 256;
            int row = i >> 3;
            int c4 = (i & 7) * 4;
            cp_async16(smem_u32(Ad + row * AP + c4),
                       A + (size_t)(brow + row) * K + k0 + c4);
        }
#pragma unroll
        for (int l = 0; l < 4; ++l) {
            int i = tid + l * 256;
            int row = i >> 5;
            int c4 = (i & 31) * 4;
            cp_async16(smem_u32(Bd + row * BP + c4),
                       B + (size_t)(k0 + row) * N + bcol + c4);
        }
        cp_commit();
    };

    load_tile(0, 0);
    load_tile(1, 1);

    int buf = 0;
    for (int it = 0; it < T; ++it) {
        if (it + 2 < T) cp_wait<1>(); else cp_wait<0>();
        __syncthreads();                    // stage `it` visible; stage (it+2)%3 free
        if (it + 2 < T) {
            int nb = buf + 2; if (nb >= 3) nb -= 3;
            load_tile(it + 2, nb);
        }

        const float* Ab = As + buf * ASZ;
        const float* Bb = Bs + buf * BSZ;
#pragma unroll
        for (int ks = 0; ks < 4; ++ks) {
            const int k = ks * 8;
            uint32_t a[4][4];
#pragma unroll
            for (int mi = 0; mi < 4; mi++) {
                int row = wm * 64 + mi * 16 + g;
                a[mi][0] = f2u(Ab[row * AP + k + tg]);
                a[mi][1] = f2u(Ab[(row + 8) * AP + k + tg]);
                a[mi][2] = f2u(Ab[row * AP + k + tg + 4]);
                a[mi][3] = f2u(Ab[(row + 8) * AP + k + tg + 4]);
            }
            uint32_t b[4][2];
#pragma unroll
            for (int ni = 0; ni < 4; ni++) {
                int col = wn * 32 + ni * 8 + g;
                b[ni][0] = f2u(Bb[(k + tg) * BP + col]);
                b[ni][1] = f2u(Bb[(k + tg + 4) * BP + col]);
            }
#pragma unroll
            for (int mi = 0; mi < 4; mi++)
#pragma unroll
                for (int ni = 0; ni < 4; ni++)
                    mma_tf32(acc[mi][ni], a[mi], b[ni][0], b[ni][1]);
        }
        buf += 1; if (buf >= 3) buf -= 3;
    }

#pragma unroll
    for (int mi = 0; mi < 4; mi++) {
#pragma unroll
        for (int ni = 0; ni < 4; ni++) {
            int row = brow + wm * 64 + mi * 16 + g;
            int col = bcol + wn * 32 + ni * 8 + tg * 2;
            *reinterpret_cast<float2*>(&C[(size_t)row * N + col]) =
                make_float2(acc[mi][ni][0], acc[mi][ni][1]);
            *reinterpret_cast<float2*>(&C[(size_t)(row + 8) * N + col]) =
                make_float2(acc[mi][ni][2], acc[mi][ni][3]);
        }
    }
}

// ---------------- causal flash attention (tf32 mma.sync) -------------------
#define AT_PA 68           // pitch for Qs/Ks/Ps (banks 4g+tg unique)
#define AT_PV 72           // pitch for Vs (banks 8tg+g unique)
#define ATTN_SMEM ((3 * 64 * AT_PA + 64 * AT_PV) * 4)

__global__ __launch_bounds__(128) void attn_mma_kernel(
        const float* __restrict__ Q, const float* __restrict__ K,
        const float* __restrict__ V, float* __restrict__ O) {
    extern __shared__ float sm[];
    float* Qs = sm;                      // [64][AT_PA]
    float* Ks = Qs + 64 * AT_PA;         // [64][AT_PA]
    float* Ps = Ks + 64 * AT_PA;         // [64][AT_PA]
    float* Vs = Ps + 64 * AT_PA;         // [64][AT_PV]

    const int qt = blockIdx.x;           // 0..31
    const int bh = blockIdx.y;           // 0..31
    const int b = bh >> 4;
    const int h = bh & 15;
    const int tid = threadIdx.x;
    const int wid = tid >> 5;
    const int lane = tid & 31;
    const int g = lane >> 2;             // 0..7
    const int tg = lane & 3;             // 0..3
    const int mrow = wid * 16;           // warp's row base in tile

    const size_t headoff = (size_t)h * DH;
    const size_t batchoff = (size_t)b * SS;

    // ---- load Q tile (scaled by 1/8, tf32-rounded) ----
    for (int i = tid; i < 64 * 16; i += 128) {
        int m = i >> 4;
        int c4 = (i & 15) * 4;
        float4 v = *reinterpret_cast<const float4*>(
            &Q[(batchoff + qt * 64 + m) * DD + headoff + c4]);
        v.x = tf32r(v.x * 0.125f); v.y = tf32r(v.y * 0.125f);
        v.z = tf32r(v.z * 0.125f); v.w = tf32r(v.w * 0.125f);
        *reinterpret_cast<float4*>(&Qs[m * AT_PA + c4]) = v;
    }
    __syncthreads();

    uint32_t qa[8][4];
#pragma unroll
    for (int kk = 0; kk < 8; ++kk) {
        int k = kk * 8;
        qa[kk][0] = f2u(Qs[(mrow + g) * AT_PA + k + tg]);
        qa[kk][1] = f2u(Qs[(mrow + g + 8) * AT_PA + k + tg]);
        qa[kk][2] = f2u(Qs[(mrow + g) * AT_PA + k + tg + 4]);
        qa[kk][3] = f2u(Qs[(mrow + g + 8) * AT_PA + k + tg + 4]);
    }

    float oacc[8][4];
#pragma unroll
    for (int j = 0; j < 8; j++)
#pragma unroll
        for (int c = 0; c < 4; c++) oacc[j][c] = 0.f;
    float m0 = -1e30f, m1 = -1e30f, l0 = 0.f, l1 = 0.f;

    for (int jt = 0; jt <= qt; ++jt) {
        for (int i = tid; i < 64 * 16; i += 128) {
            int m = i >> 4;
            int c4 = (i & 15) * 4;
            size_t src = (batchoff + jt * 64 + m) * DD + headoff + c4;
            float4 kv = *reinterpret_cast<const float4*>(&K[src]);
            kv.x = tf32r(kv.x); kv.y = tf32r(kv.y);
            kv.z = tf32r(kv.z); kv.w = tf32r(kv.w);
            *reinterpret_cast<float4*>(&Ks[m * AT_PA + c4]) = kv;
            float4 vv = *reinterpret_cast<const float4*>(&V[src]);
            vv.x = tf32r(vv.x); vv.y = tf32r(vv.y);
            vv.z = tf32r(vv.z); vv.w = tf32r(vv.w);
            *reinterpret_cast<float4*>(&Vs[m * AT_PV + c4]) = vv;
        }
        __syncthreads();

        float sacc[8][4];
#pragma unroll
        for (int j = 0; j < 8; j++)
#pragma unroll
            for (int c = 0; c < 4; c++) sacc[j][c] = 0.f;
#pragma unroll
        for (int kk = 0; kk < 8; ++kk) {
            int k = kk * 8;
            uint32_t b0[8], b1[8];
#pragma unroll
            for (int j = 0; j < 8; j++) {
                b0[j] = f2u(Ks[(j * 8 + g) * AT_PA + k + tg]);
                b1[j] = f2u(Ks[(j * 8 + g) * AT_PA + k + tg + 4]);
            }
#pragma unroll
            for (int j = 0; j < 8; j++)
                mma_tf32(sacc[j], qa[kk], b0[j], b1[j]);
        }

        if (jt == qt) {
#pragma unroll
            for (int j = 0; j < 8; j++)
#pragma unroll
                for (int c = 0; c < 2; c++) {
                    int col = j * 8 + tg * 2 + c;
                    if (col > mrow + g) sacc[j][c] = -1e30f;
                    if (col > mrow + g + 8) sacc[j][2 + c] = -1e30f;
                }
        }

        float vm0 = -1e30f, vm1 = -1e30f;
#pragma unroll
        for (int j = 0; j < 8; j++) {
            vm0 = fmaxf(vm0, fmaxf(sacc[j][0], sacc[j][1]));
            vm1 = fmaxf(vm1, fmaxf(sacc[j][2], sacc[j][3]));
        }
        vm0 = fmaxf(vm0, __shfl_xor_sync(0xffffffffu, vm0, 1));
        vm0 = fmaxf(vm0, __shfl_xor_sync(0xffffffffu, vm0, 2));
        vm1 = fmaxf(vm1, __shfl_xor_sync(0xffffffffu, vm1, 1));
        vm1 = fmaxf(vm1, __shfl_xor_sync(0xffffffffu, vm1, 2));
        float mn0 = fmaxf(m0, vm0);
        float mn1 = fmaxf(m1, vm1);
        float a0 = __expf(m0 - mn0);
        float a1 = __expf(m1 - mn1);
        float s0 = 0.f, s1 = 0.f;
#pragma unroll
        for (int j = 0; j < 8; j++) {
            int col = j * 8 + tg * 2;
            float p00 = __expf(sacc[j][0] - mn0);
            float p01 = __expf(sacc[j][1] - mn0);
            float p10 = __expf(sacc[j][2] - mn1);
            float p11 = __expf(sacc[j][3] - mn1);
            s0 += p00 + p01;
            s1 += p10 + p11;
            Ps[(mrow + g) * AT_PA + col] = tf32r(p00);
            Ps[(mrow + g) * AT_PA + col + 1] = tf32r(p01);
            Ps[(mrow + g + 8) * AT_PA + col] = tf32r(p10);
            Ps[(mrow + g + 8) * AT_PA + col + 1] = tf32r(p11);
        }
        s0 += __shfl_xor_sync(0xffffffffu, s0, 1);
        s0 += __shfl_xor_sync(0xffffffffu, s0, 2);
        s1 += __shfl_xor_sync(0xffffffffu, s1, 1);
        s1 += __shfl_xor_sync(0xffffffffu, s1, 2);
        l0 = l0 * a0 + s0;
        l1 = l1 * a1 + s1;
        m0 = mn0; m1 = mn1;
#pragma unroll
        for (int j = 0; j < 8; j++) {
            oacc[j][0] *= a0; oacc[j][1] *= a0;
            oacc[j][2] *= a1; oacc[j][3] *= a1;
        }
        __syncwarp();

#pragma unroll
        for (int kk = 0; kk < 8; ++kk) {
            int k = kk * 8;
            uint32_t pa[4];
            pa[0] = f2u(Ps[(mrow + g) * AT_PA + k + tg]);
            pa[1] = f2u(Ps[(mrow + g + 8) * AT_PA + k + tg]);
            pa[2] = f2u(Ps[(mrow + g) * AT_PA + k + tg + 4]);
            pa[3] = f2u(Ps[(mrow + g + 8) * AT_PA + k + tg + 4]);
#pragma unroll
            for (int j = 0; j < 8; j++) {
                uint32_t vb0 = f2u(Vs[(k + tg) * AT_PV + j * 8 + g]);
                uint32_t vb1 = f2u(Vs[(k + tg + 4) * AT_PV + j * 8 + g]);
                mma_tf32(oacc[j], pa, vb0, vb1);
            }
        }
        __syncthreads();
    }

    float inv0 = 1.0f / l0;
    float inv1 = 1.0f / l1;
    size_t row0 = (batchoff + qt * 64 + mrow + g) * DD + headoff;
    size_t row1 = row0 + 8 * DD;
#pragma unroll
    for (int j = 0; j < 8; j++) {
        int col = j * 8 + tg * 2;
        O[row0 + col] = tf32r(oacc[j][0] * inv0);
        O[row0 + col + 1] = tf32r(oacc[j][1] * inv0);
        O[row1 + col] = tf32r(oacc[j][2] * inv1);
        O[row1 + col + 1] = tf32r(oacc[j][3] * inv1);
    }
}

// ---------------- launch ----------------
extern "C" void kernel_launch(void* const* d_in, const int* in_sizes, int n_in,
                              void* d_out, int out_size) {
    const float* x    = (const float*)d_in[0];
    const float* wfQ  = (const float*)d_in[1];
    const float* wfK  = (const float*)d_in[2];
    const float* wfV  = (const float*)d_in[3];
    const float* wrQ  = (const float*)d_in[4];
    const float* wrK  = (const float*)d_in[5];
    const float* wrV  = (const float*)d_in[6];
    const float* f_qk = (const float*)d_in[7];
    const float* f_v  = (const float*)d_in[8];
    const float* r_qk = (const float*)d_in[9];
    const float* r_v  = (const float*)d_in[10];
    const float* W_O  = (const float*)d_in[11];
    float* out = (float*)d_out;

    float *X32, *Rqk, *Rv, *Ft, *Tt, *WH, *WHv, *QK, *Vb, *At, *WOt;
    cudaGetSymbolAddress((void**)&X32, g_x32);
    cudaGetSymbolAddress((void**)&Rqk, g_rqk);
    cudaGetSymbolAddress((void**)&Rv,  g_rv);
    cudaGetSymbolAddress((void**)&Ft,  g_Ft);
    cudaGetSymbolAddress((void**)&Tt,  g_t);
    cudaGetSymbolAddress((void**)&WH,  g_wh);
    cudaGetSymbolAddress((void**)&WHv, g_whv);
    cudaGetSymbolAddress((void**)&QK,  g_QK);
    cudaGetSymbolAddress((void**)&Vb,  g_V);
    cudaGetSymbolAddress((void**)&At,  g_At);
    cudaGetSymbolAddress((void**)&WOt, g_WOt);

    cudaFuncSetAttribute(mma_gemm_kernel,
                         cudaFuncAttributeMaxDynamicSharedMemorySize, GEMM_SMEM);
    cudaFuncSetAttribute(attn_mma_kernel,
                         cudaFuncAttributeMaxDynamicSharedMemorySize, ATTN_SMEM);

    // tf32-round GEMM operands from inputs
    to_tf32_kernel<<<(TOK * DD) / 1024, 256>>>(x, X32);
    to_tf32_kernel<<<(NR * DD) / 1024, 256>>>(r_qk, Rqk);
    to_tf32_kernel<<<(NR * DD) / 1024, 256>>>(r_v, Rv);

    // batched feature GEMM: [tqk | tv] = X @ [Fqk^T | Fv^T]  (4096 x 4096, K=1024)
    transpose_f_kernel<<<(NN * DD * RR) / 256, 256>>>(f_qk, Ft, 0);
    transpose_f_kernel<<<(NN * DD * RR) / 256, 256>>>(f_v, Ft, NR);
    mma_gemm_kernel<<<dim3(2 * NR / 128, TOK / 128), 256, GEMM_SMEM>>>(
        X32, Ft, Tt, TOK, 2 * NR, DD);

    // mixes (Q,K into stacked WH; V separate)
    mix_kernel<<<TOK, 128>>>(Tt,      wfQ, wrQ, WH,                2 * NR);
    mix_kernel<<<TOK, 128>>>(Tt,      wfK, wrK, WH + (size_t)TOK * NR, 2 * NR);
    mix_kernel<<<TOK, 128>>>(Tt + NR, wfV, wrV, WHv,               2 * NR);

    // batched Q/K restore GEMM: [Q;K] = [WHq;WHk] @ r_qk  (8192 x 1024, K=2048)
    mma_gemm_kernel<<<dim3(DD / 128, 2 * TOK / 128), 256, GEMM_SMEM>>>(
        WH, Rqk, QK, 2 * TOK, DD, NR);
    // V restore GEMM
    mma_gemm_kernel<<<dim3(DD / 128, TOK / 128), 256, GEMM_SMEM>>>(
        WHv, Rv, Vb, TOK, DD, NR);

    // causal flash attention (tensor cores)
    attn_mma_kernel<<<dim3(SS / 64, BB * HH), 128, ATTN_SMEM>>>(
        QK, QK + (size_t)TOK * DD, Vb, At);

    // out = attn @ W_O^T
    transpose_sq_kernel<<<dim3(DD / 32, DD / 32), dim3(32, 8)>>>(W_O, WOt, DD);
    mma_gemm_kernel<<<dim3(DD / 128, TOK / 128), 256, GEMM_SMEM>>>(
        At, WOt, out, TOK, DD, DD);
}